// round 7
// baseline (speedup 1.0000x reference)
#include <cuda_runtime.h>
#include <math.h>

#define N_NODES 100000
#define HDIM    64
#define CDIM    16
#define NPB     128   // nodes per block (node kernel)
#define TPB     512   // threads per block: 8 threads per node-pair
#define PAD     32    // bucket slots per (node,type) segment
#define WSTR    68    // padded stride (floats) per k-row of weight tile
#define XSTR    68    // padded stride (floats) per node row of act tiles
#define OVF_CAP 65536

typedef unsigned long long ull;

// packed f32x2 helpers (sm_103a FFMA2 path)
#define PK2(d, s)      do { unsigned _u = __float_as_uint(s); \
    asm("mov.b64 %0, {%1, %1};" : "=l"(d) : "r"(_u)); } while (0)
#define UPK2(lo, hi, s) do { unsigned _a, _b; \
    asm("mov.b64 {%0, %1}, %2;" : "=r"(_a), "=r"(_b) : "l"(s)); \
    lo = __uint_as_float(_a); hi = __uint_as_float(_b); } while (0)
#define RPK2(d, a, b)  do { unsigned _a = __float_as_uint(a), _b = __float_as_uint(b); \
    asm("mov.b64 %0, {%1, %2};" : "=l"(d) : "r"(_a), "r"(_b)); } while (0)
#define FMA2(a, w, x)  asm("fma.rn.f32x2 %0, %1, %2, %0;" : "+l"(a) : "l"(w), "l"(x))
#define MUL2(d, a, b)  asm("mul.rn.f32x2 %0, %1, %2;" : "=l"(d) : "l"(a), "l"(b))
#define ADD2(d, a, b)  asm("add.rn.f32x2 %0, %1, %2;" : "=l"(d) : "l"(a), "l"(b))

__device__ __forceinline__ float tanh_fast(float x)
{
    float t;
    asm("tanh.approx.f32 %0, %1;" : "=f"(t) : "f"(x));
    return t;
}
__device__ __forceinline__ float sigmoid_fast(float x)
{
    return 0.5f * tanh_fast(0.5f * x) + 0.5f;
}

// -------- scratch --------
__device__ float g_S0[(size_t)N_NODES * HDIM];
__device__ float g_S1[(size_t)N_NODES * HDIM];
__device__ float g_c0[N_NODES];
__device__ float g_c1[N_NODES];
__device__ int   g_cnt[2 * N_NODES];
__device__ int   g_slots[(size_t)2 * N_NODES * PAD];
__device__ int   g_et_is_i32;
__device__ int   g_ovf_n;
__device__ int2  g_ovf[OVF_CAP];

// =====================================================================
__global__ void detect_et_kernel(const unsigned char* __restrict__ et, int E)
{
    __shared__ int cnt;
    if (threadIdx.x == 0) { cnt = 0; g_ovf_n = 0; }
    __syncthreads();
    int K = 4096 < E ? 4096 : E;
    int local = 0;
    for (int i = threadIdx.x; i < K; i += blockDim.x)
        local += (et[i] != 0);
    atomicAdd(&cnt, local);
    __syncthreads();
    if (threadIdx.x == 0)
        g_et_is_i32 = (cnt < K / 4) ? 1 : 0;
}

// =====================================================================
__global__ void __launch_bounds__(256) place_kernel(
    const int*   __restrict__ src,
    const int*   __restrict__ dst,
    const void*  __restrict__ et,
    int E)
{
    int e = blockIdx.x * blockDim.x + threadIdx.x;
    if (e >= E) return;

    bool t;
    if (g_et_is_i32) t = __ldg((const int*)et + e) != 0;
    else             t = __ldg((const unsigned char*)et + e) != 0;
    int ti = t ? 0 : 1;

    int d = __ldg(dst + e);
    int s = __ldg(src + e);
    int seg = d * 2 + ti;
    int slot = atomicAdd(&g_cnt[seg], 1);
    if (slot < PAD) {
        g_slots[(size_t)seg * PAD + slot] = s;
    } else {
        int w = atomicAdd(&g_ovf_n, 1);
        if (w < OVF_CAP) g_ovf[w] = make_int2(seg, s);
    }
}

// =====================================================================
__global__ void __launch_bounds__(256) segsum_kernel(
    const float* __restrict__ feat, int Nn)
{
    int gtid = blockIdx.x * blockDim.x + threadIdx.x;
    int grp = gtid >> 4;
    int l   = gtid & 15;
    if (grp >= 2 * Nn) return;
    int d  = grp >> 1;
    int ti = grp & 1;

    int cnt = g_cnt[grp];
    int m = cnt < PAD ? cnt : PAD;
    const int* sl = g_slots + (size_t)grp * PAD;
    const float4* F = (const float4*)feat;

    float4 acc = make_float4(0.f, 0.f, 0.f, 0.f);
    int i = 0;
    for (; i + 4 <= m; i += 4) {
        int4 s4 = *(const int4*)(sl + i);
        float4 a = __ldg(F + (size_t)s4.x * 16 + l);
        float4 b = __ldg(F + (size_t)s4.y * 16 + l);
        float4 c = __ldg(F + (size_t)s4.z * 16 + l);
        float4 e = __ldg(F + (size_t)s4.w * 16 + l);
        acc.x += (a.x + b.x) + (c.x + e.x);
        acc.y += (a.y + b.y) + (c.y + e.y);
        acc.z += (a.z + b.z) + (c.z + e.z);
        acc.w += (a.w + b.w) + (c.w + e.w);
    }
    for (; i < m; i++) {
        int s = sl[i];
        float4 a = __ldg(F + (size_t)s * 16 + l);
        acc.x += a.x; acc.y += a.y; acc.z += a.z; acc.w += a.w;
    }

    float* S = ti ? g_S1 : g_S0;
    ((float4*)(S + (size_t)d * HDIM))[l] = acc;

    if (l == 0) (ti ? g_c1 : g_c0)[d] = (float)cnt;
}

// =====================================================================
__global__ void ovf_fix_kernel(const float* __restrict__ feat)
{
    int m = g_ovf_n;
    if (m > OVF_CAP) m = OVF_CAP;
    int eidx = threadIdx.x >> 4, l = threadIdx.x & 15;
    for (int i = eidx; i < m; i += 16) {
        int2 ov = g_ovf[i];
        float* S = (ov.x & 1) ? g_S1 : g_S0;
        int d = ov.x >> 1;
        float4 v = __ldg((const float4*)(feat + (size_t)ov.y * HDIM) + l);
        atomicAdd((float4*)(S + (size_t)d * HDIM) + l, v);
    }
}

// =====================================================================
// Node kernel v5: 512 threads, 8 threads per node-pair (nodes j, j+64),
// 8 outputs per thread. 2 CTAs/SM -> 32 warps (50% occ). Activation
// loads vectorized LDS.128 per 4k. FFMA2 throughout.
// =====================================================================
__device__ __forceinline__ void loadW2(float* sW, const float* __restrict__ A,
                                       const float* __restrict__ B, int row0, int tid)
{
    #pragma unroll
    for (int ii = 0; ii < 8; ii++) {
        int i = tid + ii * TPB;
        int k = i & 63, m = i >> 6;
        sW[k * WSTR + m]              = A[(row0 + m) * 64 + k];
        sW[64 * WSTR + k * WSTR + m]  = B[(row0 + m) * 64 + k];
    }
}

// acc[0..3]: node A (4 ull = 8 outputs), acc[4..7]: node B
__device__ __forceinline__ void stepA(ull* acc, const float* w, ull x0, ull x1)
{
    ulonglong2 a = *(const ulonglong2*)w;
    ulonglong2 b = *(const ulonglong2*)(w + 4);
    FMA2(acc[0], a.x, x0); FMA2(acc[1], a.y, x0);
    FMA2(acc[2], b.x, x0); FMA2(acc[3], b.y, x0);
    FMA2(acc[4], a.x, x1); FMA2(acc[5], a.y, x1);
    FMA2(acc[6], b.x, x1); FMA2(acc[7], b.y, x1);
}

__device__ __forceinline__ void stepRZ(ull* acc, const float* wa, const float* wb,
                                       ull x0, ull x1, ull f0, ull f1)
{
    ulonglong2 a  = *(const ulonglong2*)wa;
    ulonglong2 a2 = *(const ulonglong2*)(wa + 4);
    ulonglong2 b  = *(const ulonglong2*)wb;
    ulonglong2 b2 = *(const ulonglong2*)(wb + 4);
    FMA2(acc[0], a.x, x0);  FMA2(acc[1], a.y, x0);
    FMA2(acc[2], a2.x, x0); FMA2(acc[3], a2.y, x0);
    FMA2(acc[0], b.x, f0);  FMA2(acc[1], b.y, f0);
    FMA2(acc[2], b2.x, f0); FMA2(acc[3], b2.y, f0);
    FMA2(acc[4], a.x, x1);  FMA2(acc[5], a.y, x1);
    FMA2(acc[6], a2.x, x1); FMA2(acc[7], a2.y, x1);
    FMA2(acc[4], b.x, f1);  FMA2(acc[5], b.y, f1);
    FMA2(acc[6], b2.x, f1); FMA2(acc[7], b2.y, f1);
}

__device__ __forceinline__ void stepN(ull* nv, const ull* rg,
                                      const float* wa, const float* wb,
                                      ull x0, ull x1, ull f0, ull f1)
{
    ulonglong2 a  = *(const ulonglong2*)wa;
    ulonglong2 a2 = *(const ulonglong2*)(wa + 4);
    ulonglong2 b  = *(const ulonglong2*)wb;
    ulonglong2 b2 = *(const ulonglong2*)(wb + 4);
    ull t;
    FMA2(nv[0], a.x, x0);  FMA2(nv[1], a.y, x0);
    FMA2(nv[2], a2.x, x0); FMA2(nv[3], a2.y, x0);
    MUL2(t, b.x, f0);  FMA2(nv[0], t, rg[0]);
    MUL2(t, b.y, f0);  FMA2(nv[1], t, rg[1]);
    MUL2(t, b2.x, f0); FMA2(nv[2], t, rg[2]);
    MUL2(t, b2.y, f0); FMA2(nv[3], t, rg[3]);
    FMA2(nv[4], a.x, x1);  FMA2(nv[5], a.y, x1);
    FMA2(nv[6], a2.x, x1); FMA2(nv[7], a2.y, x1);
    MUL2(t, b.x, f1);  FMA2(nv[4], t, rg[4]);
    MUL2(t, b.y, f1);  FMA2(nv[5], t, rg[5]);
    MUL2(t, b2.x, f1); FMA2(nv[6], t, rg[6]);
    MUL2(t, b2.y, f1); FMA2(nv[7], t, rg[7]);
}

__global__ void __launch_bounds__(TPB, 2) node_kernel(
    const float* __restrict__ feat,
    const float* __restrict__ W0,  const float* __restrict__ b0,
    const float* __restrict__ W1,  const float* __restrict__ b1,
    const float* __restrict__ Wih, const float* __restrict__ Whh,
    const float* __restrict__ bih, const float* __restrict__ bhh,
    const float* __restrict__ Wout,const float* __restrict__ bout,
    float* __restrict__ out, int Nn)
{
    extern __shared__ float smem[];
    float* sF = smem;                    // 128*68 = 8704
    float* sX = smem + 8704;             // 8704
    float* sW = smem + 17408;            // 2*64*68 = 8704
    float* sB = smem + 26112;            // 528
    // total 26640 floats = 106560 B

    const int tid   = threadIdx.x;
    const int j     = tid & 63;          // node-pair index
    const int oq    = tid >> 6;          // output octet 0..7 (warp-uniform)
    const int mbase = oq * 8;
    const int n0    = blockIdx.x * NPB;
    const int nA    = n0 + j;
    const int nB    = n0 + j + 64;
    const int row0  = j * XSTR;
    const int row1  = (j + 64) * XSTR;

    // biases: [0:64) b0 | [64:128) b1 | [128:320) bih | [320:512) bhh | [512:528) bout
    for (int i = tid; i < 528; i += TPB) {
        float v;
        if (i < 64)       v = b0[i];
        else if (i < 128) v = b1[i - 64];
        else if (i < 320) v = bih[i - 128];
        else if (i < 512) v = bhh[i - 320];
        else              v = bout[i - 512];
        sB[i] = v;
    }
    // stage feat + S0 (float4 LDG, float4 STS — rows 16B aligned at stride 68)
    {
        const float4 z4 = make_float4(0.f, 0.f, 0.f, 0.f);
        const float4* f4 = (const float4*)feat;
        const float4* s04 = (const float4*)g_S0;
        #pragma unroll
        for (int ii = 0; ii < 4; ii++) {
            int i = tid + ii * TPB;
            int r = i >> 4, c4 = i & 15;
            int nn = n0 + r;
            float4 vf = (nn < Nn) ? __ldg(f4 + (size_t)nn * 16 + c4) : z4;
            float4 vs = (nn < Nn) ? __ldg(s04 + (size_t)nn * 16 + c4) : z4;
            *(float4*)(sF + r * XSTR + c4 * 4) = vf;
            *(float4*)(sX + r * XSTR + c4 * 4) = vs;
        }
    }
    loadW2(sW, W0, W1, 0, tid);

    // prefetch S1 tile into registers (hidden behind agg pass 1)
    float4 s1pre[4];
    {
        const float4 z4 = make_float4(0.f, 0.f, 0.f, 0.f);
        const float4* s14 = (const float4*)g_S1;
        #pragma unroll
        for (int ii = 0; ii < 4; ii++) {
            int i = tid + ii * TPB;
            int r = i >> 4, c4 = i & 15;
            int nn = n0 + r;
            s1pre[ii] = (nn < Nn) ? __ldg(s14 + (size_t)nn * 16 + c4) : z4;
        }
    }
    __syncthreads();

    // ---- agg ----
    ull acc[8];
    {
        float c0a = (nA < Nn) ? g_c0[nA] : 0.f;
        float c1a = (nA < Nn) ? g_c1[nA] : 0.f;
        float c0b = (nB < Nn) ? g_c0[nB] : 0.f;
        float c1b = (nB < Nn) ? g_c1[nB] : 0.f;
        ull c0a2, c1a2, c0b2, c1b2;
        PK2(c0a2, c0a); PK2(c1a2, c1a); PK2(c0b2, c0b); PK2(c1b2, c1b);
        const ull* pb0 = (const ull*)(sB + mbase);
        const ull* pb1 = (const ull*)(sB + 64 + mbase);
        #pragma unroll
        for (int q = 0; q < 4; q++) {
            MUL2(acc[q],   c0a2, pb0[q]); FMA2(acc[q],   c1a2, pb1[q]);
            MUL2(acc[4+q], c0b2, pb0[q]); FMA2(acc[4+q], c1b2, pb1[q]);
        }
    }
    #pragma unroll 2
    for (int k4 = 0; k4 < 16; k4++) {
        float4 xv0 = *(const float4*)(sX + row0 + k4 * 4);
        float4 xv1 = *(const float4*)(sX + row1 + k4 * 4);
        const float* w = sW + (k4 * 4) * WSTR + mbase;
        ull x0, x1;
        PK2(x0, xv0.x); PK2(x1, xv1.x); stepA(acc, w,            x0, x1);
        PK2(x0, xv0.y); PK2(x1, xv1.y); stepA(acc, w + WSTR,     x0, x1);
        PK2(x0, xv0.z); PK2(x1, xv1.z); stepA(acc, w + 2 * WSTR, x0, x1);
        PK2(x0, xv0.w); PK2(x1, xv1.w); stepA(acc, w + 3 * WSTR, x0, x1);
    }
    __syncthreads();
    #pragma unroll
    for (int ii = 0; ii < 4; ii++) {
        int i = tid + ii * TPB;
        int r = i >> 4, c4 = i & 15;
        *(float4*)(sX + r * XSTR + c4 * 4) = s1pre[ii];
    }
    __syncthreads();
    #pragma unroll 2
    for (int k4 = 0; k4 < 16; k4++) {
        float4 xv0 = *(const float4*)(sX + row0 + k4 * 4);
        float4 xv1 = *(const float4*)(sX + row1 + k4 * 4);
        const float* w = sW + 64 * WSTR + (k4 * 4) * WSTR + mbase;
        ull x0, x1;
        PK2(x0, xv0.x); PK2(x1, xv1.x); stepA(acc, w,            x0, x1);
        PK2(x0, xv0.y); PK2(x1, xv1.y); stepA(acc, w + WSTR,     x0, x1);
        PK2(x0, xv0.z); PK2(x1, xv1.z); stepA(acc, w + 2 * WSTR, x0, x1);
        PK2(x0, xv0.w); PK2(x1, xv1.w); stepA(acc, w + 3 * WSTR, x0, x1);
    }
    __syncthreads();
    // park agg (STS.64, own cells)
    #pragma unroll
    for (int q = 0; q < 4; q++) {
        *(ull*)(sX + row0 + mbase + 2 * q) = acc[q];
        *(ull*)(sX + row1 + mbase + 2 * q) = acc[4 + q];
    }
    loadW2(sW, Wih, Whh, 0, tid);
    __syncthreads();

    // ---- r gate ----
    ull rg[8];
    {
        const ull* pbi = (const ull*)(sB + 128 + mbase);
        const ull* pbh = (const ull*)(sB + 320 + mbase);
        #pragma unroll
        for (int q = 0; q < 4; q++) { ADD2(rg[q], pbi[q], pbh[q]); rg[4+q] = rg[q]; }
    }
    #pragma unroll 2
    for (int k4 = 0; k4 < 16; k4++) {
        float4 xv0 = *(const float4*)(sX + row0 + k4 * 4);
        float4 xv1 = *(const float4*)(sX + row1 + k4 * 4);
        float4 fv0 = *(const float4*)(sF + row0 + k4 * 4);
        float4 fv1 = *(const float4*)(sF + row1 + k4 * 4);
        const float* wa = sW + (k4 * 4) * WSTR + mbase;
        const float* wb = wa + 64 * WSTR;
        ull x0, x1, f0, f1;
        PK2(x0, xv0.x); PK2(x1, xv1.x); PK2(f0, fv0.x); PK2(f1, fv1.x);
        stepRZ(rg, wa, wb, x0, x1, f0, f1);
        PK2(x0, xv0.y); PK2(x1, xv1.y); PK2(f0, fv0.y); PK2(f1, fv1.y);
        stepRZ(rg, wa + WSTR, wb + WSTR, x0, x1, f0, f1);
        PK2(x0, xv0.z); PK2(x1, xv1.z); PK2(f0, fv0.z); PK2(f1, fv1.z);
        stepRZ(rg, wa + 2 * WSTR, wb + 2 * WSTR, x0, x1, f0, f1);
        PK2(x0, xv0.w); PK2(x1, xv1.w); PK2(f0, fv0.w); PK2(f1, fv1.w);
        stepRZ(rg, wa + 3 * WSTR, wb + 3 * WSTR, x0, x1, f0, f1);
    }
    #pragma unroll
    for (int q = 0; q < 8; q++) {
        float lo, hi; UPK2(lo, hi, rg[q]);
        lo = sigmoid_fast(lo); hi = sigmoid_fast(hi);
        RPK2(rg[q], lo, hi);
    }

    // ---- n gate ----
    __syncthreads();
    loadW2(sW, Wih, Whh, 128, tid);
    __syncthreads();
    ull nv[8];
    {
        const ull* pbi = (const ull*)(sB + 256 + mbase);
        const ull* pbh = (const ull*)(sB + 448 + mbase);
        #pragma unroll
        for (int q = 0; q < 4; q++) {
            nv[q] = pbi[q];   FMA2(nv[q],   rg[q],   pbh[q]);
            nv[4+q] = pbi[q]; FMA2(nv[4+q], rg[4+q], pbh[q]);
        }
    }
    #pragma unroll 2
    for (int k4 = 0; k4 < 16; k4++) {
        float4 xv0 = *(const float4*)(sX + row0 + k4 * 4);
        float4 xv1 = *(const float4*)(sX + row1 + k4 * 4);
        float4 fv0 = *(const float4*)(sF + row0 + k4 * 4);
        float4 fv1 = *(const float4*)(sF + row1 + k4 * 4);
        const float* wa = sW + (k4 * 4) * WSTR + mbase;
        const float* wb = wa + 64 * WSTR;
        ull x0, x1, f0, f1;
        PK2(x0, xv0.x); PK2(x1, xv1.x); PK2(f0, fv0.x); PK2(f1, fv1.x);
        stepN(nv, rg, wa, wb, x0, x1, f0, f1);
        PK2(x0, xv0.y); PK2(x1, xv1.y); PK2(f0, fv0.y); PK2(f1, fv1.y);
        stepN(nv, rg, wa + WSTR, wb + WSTR, x0, x1, f0, f1);
        PK2(x0, xv0.z); PK2(x1, xv1.z); PK2(f0, fv0.z); PK2(f1, fv1.z);
        stepN(nv, rg, wa + 2 * WSTR, wb + 2 * WSTR, x0, x1, f0, f1);
        PK2(x0, xv0.w); PK2(x1, xv1.w); PK2(f0, fv0.w); PK2(f1, fv1.w);
        stepN(nv, rg, wa + 3 * WSTR, wb + 3 * WSTR, x0, x1, f0, f1);
    }
    #pragma unroll
    for (int q = 0; q < 8; q++) {
        float lo, hi; UPK2(lo, hi, nv[q]);
        lo = tanh_fast(lo); hi = tanh_fast(hi);
        RPK2(nv[q], lo, hi);
    }

    // ---- z gate ----
    __syncthreads();
    loadW2(sW, Wih, Whh, 64, tid);
    __syncthreads();
    ull zg[8];
    {
        const ull* pbi = (const ull*)(sB + 192 + mbase);
        const ull* pbh = (const ull*)(sB + 384 + mbase);
        #pragma unroll
        for (int q = 0; q < 4; q++) { ADD2(zg[q], pbi[q], pbh[q]); zg[4+q] = zg[q]; }
    }
    #pragma unroll 2
    for (int k4 = 0; k4 < 16; k4++) {
        float4 xv0 = *(const float4*)(sX + row0 + k4 * 4);
        float4 xv1 = *(const float4*)(sX + row1 + k4 * 4);
        float4 fv0 = *(const float4*)(sF + row0 + k4 * 4);
        float4 fv1 = *(const float4*)(sF + row1 + k4 * 4);
        const float* wa = sW + (k4 * 4) * WSTR + mbase;
        const float* wb = wa + 64 * WSTR;
        ull x0, x1, f0, f1;
        PK2(x0, xv0.x); PK2(x1, xv1.x); PK2(f0, fv0.x); PK2(f1, fv1.x);
        stepRZ(zg, wa, wb, x0, x1, f0, f1);
        PK2(x0, xv0.y); PK2(x1, xv1.y); PK2(f0, fv0.y); PK2(f1, fv1.y);
        stepRZ(zg, wa + WSTR, wb + WSTR, x0, x1, f0, f1);
        PK2(x0, xv0.z); PK2(x1, xv1.z); PK2(f0, fv0.z); PK2(f1, fv1.z);
        stepRZ(zg, wa + 2 * WSTR, wb + 2 * WSTR, x0, x1, f0, f1);
        PK2(x0, xv0.w); PK2(x1, xv1.w); PK2(f0, fv0.w); PK2(f1, fv1.w);
        stepRZ(zg, wa + 3 * WSTR, wb + 3 * WSTR, x0, x1, f0, f1);
    }
    __syncthreads();   // all gate reads of sX done
    // h = n + z*(f - n); park into sX (STS.64)
    #pragma unroll
    for (int q = 0; q < 8; q++) {
        const int row = (q < 4) ? row0 : row1;
        const int mq  = mbase + 2 * (q & 3);
        float zlo, zhi, nlo, nhi;
        UPK2(zlo, zhi, zg[q]); UPK2(nlo, nhi, nv[q]);
        zlo = sigmoid_fast(zlo); zhi = sigmoid_fast(zhi);
        float h0 = nlo + zlo * (sF[row + mq]     - nlo);
        float h1 = nhi + zhi * (sF[row + mq + 1] - nhi);
        ull hp; RPK2(hp, h0, h1);
        *(ull*)(sX + row + mq) = hp;
    }
    // stage classifier weights
    for (int i = tid; i < 1024; i += TPB) {
        int k = i & 63, c = i >> 6;
        sW[k * 16 + c] = Wout[c * 64 + k];
    }
    __syncthreads();

    // ---- classifier: 2 nodes x 2 classes per thread ----
    float oA[2], oB[2];
    oA[0] = sB[512 + oq * 2];     oB[0] = oA[0];
    oA[1] = sB[512 + oq * 2 + 1]; oB[1] = oA[1];
    #pragma unroll 4
    for (int k4 = 0; k4 < 16; k4++) {
        float4 h0 = *(const float4*)(sX + row0 + k4 * 4);
        float4 h1 = *(const float4*)(sX + row1 + k4 * 4);
        const float* w = sW + (k4 * 4) * 16 + oq * 2;
        float2 w0 = *(const float2*)(w);
        float2 w1 = *(const float2*)(w + 16);
        float2 w2 = *(const float2*)(w + 32);
        float2 w3 = *(const float2*)(w + 48);
        oA[0] += h0.x * w0.x + h0.y * w1.x + h0.z * w2.x + h0.w * w3.x;
        oA[1] += h0.x * w0.y + h0.y * w1.y + h0.z * w2.y + h0.w * w3.y;
        oB[0] += h1.x * w0.x + h1.y * w1.x + h1.z * w2.x + h1.w * w3.x;
        oB[1] += h1.x * w0.y + h1.y * w1.y + h1.z * w2.y + h1.w * w3.y;
    }
    if (nA < Nn)
        *(float2*)(out + (size_t)nA * 16 + oq * 2) = make_float2(oA[0], oA[1]);
    if (nB < Nn)
        *(float2*)(out + (size_t)nB * 16 + oq * 2) = make_float2(oB[0], oB[1]);
}

// =====================================================================
extern "C" void kernel_launch(void* const* d_in, const int* in_sizes, int n_in,
                              void* d_out, int out_size)
{
    const float* feat = (const float*)d_in[0];
    const int*   src  = (const int*)d_in[1];
    const int*   dst  = (const int*)d_in[2];
    const void*  et   = d_in[3];
    const float* W0   = (const float*)d_in[4];
    const float* b0   = (const float*)d_in[5];
    const float* W1   = (const float*)d_in[6];
    const float* b1   = (const float*)d_in[7];
    const float* Wih  = (const float*)d_in[8];
    const float* Whh  = (const float*)d_in[9];
    const float* bih  = (const float*)d_in[10];
    const float* bhh  = (const float*)d_in[11];
    const float* Wout = (const float*)d_in[12];
    const float* bout = (const float*)d_in[13];
    float* out = (float*)d_out;

    const int E  = in_sizes[1];
    const int Nn = in_sizes[0] / HDIM;

    void* p;
    cudaGetSymbolAddress(&p, g_cnt);
    cudaMemsetAsync(p, 0, sizeof(int) * 2 * N_NODES);

    detect_et_kernel<<<1, 256>>>((const unsigned char*)et, E);

    place_kernel<<<(E + 255) / 256, 256>>>(src, dst, et, E);

    {
        long long tot = (long long)(2 * Nn) * 16;
        int blocks = (int)((tot + 255) / 256);
        segsum_kernel<<<blocks, 256>>>(feat, Nn);
    }
    ovf_fix_kernel<<<1, 256>>>(feat);
    {
        size_t smem = (size_t)(8704 * 3 + 528) * sizeof(float); // 106560 B
        cudaFuncSetAttribute(node_kernel, cudaFuncAttributeMaxDynamicSharedMemorySize, (int)smem);
        int nb = (Nn + NPB - 1) / NPB;
        node_kernel<<<nb, TPB, smem>>>(feat, W0, b0, W1, b1, Wih, Whh,
                                       bih, bhh, Wout, bout, out, Nn);
    }
}

// round 8
// speedup vs baseline: 1.0342x; 1.0342x over previous
#include <cuda_runtime.h>
#include <math.h>

#define N_NODES 100000
#define HDIM    64
#define CDIM    16
#define NPB     128   // nodes per block (node kernel)
#define TPB     256   // threads per block: 4 threads per node-pair
#define PAD     32    // bucket slots per (node,type) segment
#define WSTR    68    // padded stride (floats) per k-row of weight tile
#define XSTR    68    // padded stride (floats) per node row of act tiles
#define OVF_CAP 65536

typedef unsigned long long ull;

// packed f32x2 helpers (sm_103a FFMA2 path)
#define PK2(d, s)      do { unsigned _u = __float_as_uint(s); \
    asm("mov.b64 %0, {%1, %1};" : "=l"(d) : "r"(_u)); } while (0)
#define UPK2(lo, hi, s) do { unsigned _a, _b; \
    asm("mov.b64 {%0, %1}, %2;" : "=r"(_a), "=r"(_b) : "l"(s)); \
    lo = __uint_as_float(_a); hi = __uint_as_float(_b); } while (0)
#define RPK2(d, a, b)  do { unsigned _a = __float_as_uint(a), _b = __float_as_uint(b); \
    asm("mov.b64 %0, {%1, %2};" : "=l"(d) : "r"(_a), "r"(_b)); } while (0)
#define FMA2(a, w, x)  asm("fma.rn.f32x2 %0, %1, %2, %0;" : "+l"(a) : "l"(w), "l"(x))
#define MUL2(d, a, b)  asm("mul.rn.f32x2 %0, %1, %2;" : "=l"(d) : "l"(a), "l"(b))
#define ADD2(d, a, b)  asm("add.rn.f32x2 %0, %1, %2;" : "=l"(d) : "l"(a), "l"(b))

__device__ __forceinline__ float tanh_fast(float x)
{
    float t;
    asm("tanh.approx.f32 %0, %1;" : "=f"(t) : "f"(x));
    return t;
}
__device__ __forceinline__ float sigmoid_fast(float x)
{
    return 0.5f * tanh_fast(0.5f * x) + 0.5f;
}

// -------- scratch --------
__device__ int   g_cnt[2 * N_NODES];
__device__ int   g_slots[(size_t)2 * N_NODES * PAD];
__device__ int   g_et_is_i32;
__device__ int   g_ovf_n;
__device__ int2  g_ovf[OVF_CAP];

// =====================================================================
__global__ void detect_et_kernel(const unsigned char* __restrict__ et, int E)
{
    __shared__ int cnt;
    if (threadIdx.x == 0) { cnt = 0; g_ovf_n = 0; }
    __syncthreads();
    int K = 4096 < E ? 4096 : E;
    int local = 0;
    for (int i = threadIdx.x; i < K; i += blockDim.x)
        local += (et[i] != 0);
    atomicAdd(&cnt, local);
    __syncthreads();
    if (threadIdx.x == 0)
        g_et_is_i32 = (cnt < K / 4) ? 1 : 0;
}

// =====================================================================
__global__ void __launch_bounds__(256) place_kernel(
    const int*   __restrict__ src,
    const int*   __restrict__ dst,
    const void*  __restrict__ et,
    int E)
{
    int e = blockIdx.x * blockDim.x + threadIdx.x;
    if (e >= E) return;

    bool t;
    if (g_et_is_i32) t = __ldg((const int*)et + e) != 0;
    else             t = __ldg((const unsigned char*)et + e) != 0;
    int ti = t ? 0 : 1;

    int d = __ldg(dst + e);
    int s = __ldg(src + e);
    int seg = d * 2 + ti;
    int slot = atomicAdd(&g_cnt[seg], 1);
    if (slot < PAD) {
        g_slots[(size_t)seg * PAD + slot] = s;
    } else {
        int w = atomicAdd(&g_ovf_n, 1);
        if (w < OVF_CAP) g_ovf[w] = make_int2(seg, s);
    }
}

// =====================================================================
// Node kernel v6: fused gather + agg + GRU + classifier.
// TPB=256, 4 threads per node-pair (nodes j, j+64), 16 outputs per
// thread per node. 2 CTAs/SM. Vectorized activation LDS, FFMA2 math.
// =====================================================================
__device__ __forceinline__ void loadW2(float* sW, const float* __restrict__ A,
                                       const float* __restrict__ B, int row0, int tid)
{
    #pragma unroll
    for (int ii = 0; ii < 16; ii++) {
        int i = tid + ii * TPB;
        int k = i & 63, m = i >> 6;
        sW[k * WSTR + m]              = A[(row0 + m) * 64 + k];
        sW[64 * WSTR + k * WSTR + m]  = B[(row0 + m) * 64 + k];
    }
}

// gather one type's segment sums for this CTA's 128 nodes into dstX
__device__ __forceinline__ void gather_seg(float* dstX, const float4* __restrict__ F,
                                           int n0, int ti, int Nn, int tid)
{
    #pragma unroll
    for (int it = 0; it < 8; it++) {
        int idx = tid + it * TPB;        // 0..2047
        int r = idx >> 4, l = idx & 15;
        int nn = n0 + r;
        float4 acc = make_float4(0.f, 0.f, 0.f, 0.f);
        if (nn < Nn) {
            int seg = nn * 2 + ti;
            int cnt = g_cnt[seg];
            int m = cnt < PAD ? cnt : PAD;
            const int* sl = g_slots + (size_t)seg * PAD;
            int i = 0;
            for (; i + 4 <= m; i += 4) {
                int4 s4 = *(const int4*)(sl + i);
                float4 a = __ldg(F + (size_t)s4.x * 16 + l);
                float4 b = __ldg(F + (size_t)s4.y * 16 + l);
                float4 c = __ldg(F + (size_t)s4.z * 16 + l);
                float4 e = __ldg(F + (size_t)s4.w * 16 + l);
                acc.x += (a.x + b.x) + (c.x + e.x);
                acc.y += (a.y + b.y) + (c.y + e.y);
                acc.z += (a.z + b.z) + (c.z + e.z);
                acc.w += (a.w + b.w) + (c.w + e.w);
            }
            for (; i < m; i++) {
                int s = sl[i];
                float4 a = __ldg(F + (size_t)s * 16 + l);
                acc.x += a.x; acc.y += a.y; acc.z += a.z; acc.w += a.w;
            }
        }
        *(float4*)(dstX + r * XSTR + l * 4) = acc;
    }
    // overflow fixup (normally g_ovf_n == 0 -> skipped)
    int mo = g_ovf_n;
    if (mo > 0) {
        if (mo > OVF_CAP) mo = OVF_CAP;
        for (int i = tid; i < mo * 16; i += TPB) {
            int ei = i >> 4, l = i & 15;
            int2 ov = g_ovf[ei];
            int t2 = ov.x & 1, d = ov.x >> 1;
            if (t2 == ti && d >= n0 && d < n0 + NPB) {
                float4 v = __ldg(F + (size_t)ov.y * 16 + l);
                float* p = dstX + (d - n0) * XSTR + l * 4;
                atomicAdd(p + 0, v.x); atomicAdd(p + 1, v.y);
                atomicAdd(p + 2, v.z); atomicAdd(p + 3, v.w);
            }
        }
    }
}

// acc[0..7]: node A (16 outputs), acc[8..15]: node B
__device__ __forceinline__ void stepA16(ull* acc, const float* w, ull x0, ull x1)
{
    ulonglong2 w01 = *(const ulonglong2*)w;
    ulonglong2 w23 = *(const ulonglong2*)(w + 4);
    ulonglong2 w45 = *(const ulonglong2*)(w + 8);
    ulonglong2 w67 = *(const ulonglong2*)(w + 12);
    FMA2(acc[0], w01.x, x0); FMA2(acc[1], w01.y, x0);
    FMA2(acc[2], w23.x, x0); FMA2(acc[3], w23.y, x0);
    FMA2(acc[4], w45.x, x0); FMA2(acc[5], w45.y, x0);
    FMA2(acc[6], w67.x, x0); FMA2(acc[7], w67.y, x0);
    FMA2(acc[8],  w01.x, x1); FMA2(acc[9],  w01.y, x1);
    FMA2(acc[10], w23.x, x1); FMA2(acc[11], w23.y, x1);
    FMA2(acc[12], w45.x, x1); FMA2(acc[13], w45.y, x1);
    FMA2(acc[14], w67.x, x1); FMA2(acc[15], w67.y, x1);
}

__device__ __forceinline__ void stepG16(ull* g, const float* wa, const float* wb,
                                        ull x0, ull x1, ull f0, ull f1)
{
    ulonglong2 a01 = *(const ulonglong2*)wa;
    ulonglong2 a23 = *(const ulonglong2*)(wa + 4);
    ulonglong2 a45 = *(const ulonglong2*)(wa + 8);
    ulonglong2 a67 = *(const ulonglong2*)(wa + 12);
    FMA2(g[0], a01.x, x0); FMA2(g[1], a01.y, x0);
    FMA2(g[2], a23.x, x0); FMA2(g[3], a23.y, x0);
    FMA2(g[4], a45.x, x0); FMA2(g[5], a45.y, x0);
    FMA2(g[6], a67.x, x0); FMA2(g[7], a67.y, x0);
    FMA2(g[8],  a01.x, x1); FMA2(g[9],  a01.y, x1);
    FMA2(g[10], a23.x, x1); FMA2(g[11], a23.y, x1);
    FMA2(g[12], a45.x, x1); FMA2(g[13], a45.y, x1);
    FMA2(g[14], a67.x, x1); FMA2(g[15], a67.y, x1);
    ulonglong2 b01 = *(const ulonglong2*)wb;
    ulonglong2 b23 = *(const ulonglong2*)(wb + 4);
    ulonglong2 b45 = *(const ulonglong2*)(wb + 8);
    ulonglong2 b67 = *(const ulonglong2*)(wb + 12);
    FMA2(g[0], b01.x, f0); FMA2(g[1], b01.y, f0);
    FMA2(g[2], b23.x, f0); FMA2(g[3], b23.y, f0);
    FMA2(g[4], b45.x, f0); FMA2(g[5], b45.y, f0);
    FMA2(g[6], b67.x, f0); FMA2(g[7], b67.y, f0);
    FMA2(g[8],  b01.x, f1); FMA2(g[9],  b01.y, f1);
    FMA2(g[10], b23.x, f1); FMA2(g[11], b23.y, f1);
    FMA2(g[12], b45.x, f1); FMA2(g[13], b45.y, f1);
    FMA2(g[14], b67.x, f1); FMA2(g[15], b67.y, f1);
}

__device__ __forceinline__ void stepN16(ull* nv, const ull* rg,
                                        const float* wa, const float* wb,
                                        ull x0, ull x1, ull f0, ull f1)
{
    ulonglong2 a01 = *(const ulonglong2*)wa;
    ulonglong2 a23 = *(const ulonglong2*)(wa + 4);
    ulonglong2 a45 = *(const ulonglong2*)(wa + 8);
    ulonglong2 a67 = *(const ulonglong2*)(wa + 12);
    FMA2(nv[0], a01.x, x0); FMA2(nv[1], a01.y, x0);
    FMA2(nv[2], a23.x, x0); FMA2(nv[3], a23.y, x0);
    FMA2(nv[4], a45.x, x0); FMA2(nv[5], a45.y, x0);
    FMA2(nv[6], a67.x, x0); FMA2(nv[7], a67.y, x0);
    FMA2(nv[8],  a01.x, x1); FMA2(nv[9],  a01.y, x1);
    FMA2(nv[10], a23.x, x1); FMA2(nv[11], a23.y, x1);
    FMA2(nv[12], a45.x, x1); FMA2(nv[13], a45.y, x1);
    FMA2(nv[14], a67.x, x1); FMA2(nv[15], a67.y, x1);
    ulonglong2 b01 = *(const ulonglong2*)wb;
    ulonglong2 b23 = *(const ulonglong2*)(wb + 4);
    ulonglong2 b45 = *(const ulonglong2*)(wb + 8);
    ulonglong2 b67 = *(const ulonglong2*)(wb + 12);
    ull t;
    MUL2(t, b01.x, f0); FMA2(nv[0], t, rg[0]);
    MUL2(t, b01.y, f0); FMA2(nv[1], t, rg[1]);
    MUL2(t, b23.x, f0); FMA2(nv[2], t, rg[2]);
    MUL2(t, b23.y, f0); FMA2(nv[3], t, rg[3]);
    MUL2(t, b45.x, f0); FMA2(nv[4], t, rg[4]);
    MUL2(t, b45.y, f0); FMA2(nv[5], t, rg[5]);
    MUL2(t, b67.x, f0); FMA2(nv[6], t, rg[6]);
    MUL2(t, b67.y, f0); FMA2(nv[7], t, rg[7]);
    MUL2(t, b01.x, f1); FMA2(nv[8],  t, rg[8]);
    MUL2(t, b01.y, f1); FMA2(nv[9],  t, rg[9]);
    MUL2(t, b23.x, f1); FMA2(nv[10], t, rg[10]);
    MUL2(t, b23.y, f1); FMA2(nv[11], t, rg[11]);
    MUL2(t, b45.x, f1); FMA2(nv[12], t, rg[12]);
    MUL2(t, b45.y, f1); FMA2(nv[13], t, rg[13]);
    MUL2(t, b67.x, f1); FMA2(nv[14], t, rg[14]);
    MUL2(t, b67.y, f1); FMA2(nv[15], t, rg[15]);
}

__global__ void __launch_bounds__(TPB, 2) node_kernel(
    const float* __restrict__ feat,
    const float* __restrict__ W0,  const float* __restrict__ b0,
    const float* __restrict__ W1,  const float* __restrict__ b1,
    const float* __restrict__ Wih, const float* __restrict__ Whh,
    const float* __restrict__ bih, const float* __restrict__ bhh,
    const float* __restrict__ Wout,const float* __restrict__ bout,
    float* __restrict__ out, int Nn)
{
    extern __shared__ float smem[];
    float* sF = smem;                    // 128*68 = 8704
    float* sX = smem + 8704;             // 8704
    float* sW = smem + 17408;            // 8704
    float* sB = smem + 26112;            // 528
    // total 26640 floats = 106560 B

    const int tid   = threadIdx.x;
    const int j     = tid & 63;
    const int oq    = tid >> 6;          // 0..3, warp-uniform
    const int mbase = oq * 16;
    const int n0    = blockIdx.x * NPB;
    const int nA    = n0 + j;
    const int nB    = n0 + j + 64;
    const int row0  = j * XSTR;
    const int row1  = (j + 64) * XSTR;
    const float4* F = (const float4*)feat;

    // biases: [0:64) b0 | [64:128) b1 | [128:320) bih | [320:512) bhh | [512:528) bout
    for (int i = tid; i < 528; i += TPB) {
        float v;
        if (i < 64)       v = b0[i];
        else if (i < 128) v = b1[i - 64];
        else if (i < 320) v = bih[i - 128];
        else if (i < 512) v = bhh[i - 320];
        else              v = bout[i - 512];
        sB[i] = v;
    }
    // stage feat tile
    {
        const float4 z4 = make_float4(0.f, 0.f, 0.f, 0.f);
        #pragma unroll
        for (int ii = 0; ii < 8; ii++) {
            int i = tid + ii * TPB;
            int r = i >> 4, c4 = i & 15;
            int nn = n0 + r;
            float4 vf = (nn < Nn) ? __ldg(F + (size_t)nn * 16 + c4) : z4;
            *(float4*)(sF + r * XSTR + c4 * 4) = vf;
        }
    }
    loadW2(sW, W0, W1, 0, tid);
    // gather S0 into sX
    gather_seg(sX, F, n0, 0, Nn, tid);
    __syncthreads();

    // ---- agg ----
    ull acc[16];
    {
        float c0a = (nA < Nn) ? (float)g_cnt[nA * 2]     : 0.f;
        float c1a = (nA < Nn) ? (float)g_cnt[nA * 2 + 1] : 0.f;
        float c0b = (nB < Nn) ? (float)g_cnt[nB * 2]     : 0.f;
        float c1b = (nB < Nn) ? (float)g_cnt[nB * 2 + 1] : 0.f;
        ull c0a2, c1a2, c0b2, c1b2;
        PK2(c0a2, c0a); PK2(c1a2, c1a); PK2(c0b2, c0b); PK2(c1b2, c1b);
        const ull* pb0 = (const ull*)(sB + mbase);
        const ull* pb1 = (const ull*)(sB + 64 + mbase);
        #pragma unroll
        for (int q = 0; q < 8; q++) {
            MUL2(acc[q],   c0a2, pb0[q]); FMA2(acc[q],   c1a2, pb1[q]);
            MUL2(acc[8+q], c0b2, pb0[q]); FMA2(acc[8+q], c1b2, pb1[q]);
        }
    }
    #pragma unroll 2
    for (int k4 = 0; k4 < 16; k4++) {
        float4 xv0 = *(const float4*)(sX + row0 + k4 * 4);
        float4 xv1 = *(const float4*)(sX + row1 + k4 * 4);
        const float* w = sW + (k4 * 4) * WSTR + mbase;
        ull x0, x1;
        PK2(x0, xv0.x); PK2(x1, xv1.x); stepA16(acc, w,            x0, x1);
        PK2(x0, xv0.y); PK2(x1, xv1.y); stepA16(acc, w + WSTR,     x0, x1);
        PK2(x0, xv0.z); PK2(x1, xv1.z); stepA16(acc, w + 2 * WSTR, x0, x1);
        PK2(x0, xv0.w); PK2(x1, xv1.w); stepA16(acc, w + 3 * WSTR, x0, x1);
    }
    __syncthreads();
    // gather S1 into sX (overwrite)
    gather_seg(sX, F, n0, 1, Nn, tid);
    __syncthreads();
    #pragma unroll 2
    for (int k4 = 0; k4 < 16; k4++) {
        float4 xv0 = *(const float4*)(sX + row0 + k4 * 4);
        float4 xv1 = *(const float4*)(sX + row1 + k4 * 4);
        const float* w = sW + 64 * WSTR + (k4 * 4) * WSTR + mbase;
        ull x0, x1;
        PK2(x0, xv0.x); PK2(x1, xv1.x); stepA16(acc, w,            x0, x1);
        PK2(x0, xv0.y); PK2(x1, xv1.y); stepA16(acc, w + WSTR,     x0, x1);
        PK2(x0, xv0.z); PK2(x1, xv1.z); stepA16(acc, w + 2 * WSTR, x0, x1);
        PK2(x0, xv0.w); PK2(x1, xv1.w); stepA16(acc, w + 3 * WSTR, x0, x1);
    }
    __syncthreads();
    // park agg (STS.64, own cells)
    #pragma unroll
    for (int q = 0; q < 8; q++) {
        *(ull*)(sX + row0 + mbase + 2 * q) = acc[q];
        *(ull*)(sX + row1 + mbase + 2 * q) = acc[8 + q];
    }
    loadW2(sW, Wih, Whh, 0, tid);
    __syncthreads();

    // ---- r gate ----
    ull rg[16];
    {
        const ull* pbi = (const ull*)(sB + 128 + mbase);
        const ull* pbh = (const ull*)(sB + 320 + mbase);
        #pragma unroll
        for (int q = 0; q < 8; q++) { ADD2(rg[q], pbi[q], pbh[q]); rg[8+q] = rg[q]; }
    }
    #pragma unroll 2
    for (int k4 = 0; k4 < 16; k4++) {
        float4 xv0 = *(const float4*)(sX + row0 + k4 * 4);
        float4 xv1 = *(const float4*)(sX + row1 + k4 * 4);
        float4 fv0 = *(const float4*)(sF + row0 + k4 * 4);
        float4 fv1 = *(const float4*)(sF + row1 + k4 * 4);
        const float* wa = sW + (k4 * 4) * WSTR + mbase;
        const float* wb = wa + 64 * WSTR;
        ull x0, x1, f0, f1;
        PK2(x0, xv0.x); PK2(x1, xv1.x); PK2(f0, fv0.x); PK2(f1, fv1.x);
        stepG16(rg, wa, wb, x0, x1, f0, f1);
        PK2(x0, xv0.y); PK2(x1, xv1.y); PK2(f0, fv0.y); PK2(f1, fv1.y);
        stepG16(rg, wa + WSTR, wb + WSTR, x0, x1, f0, f1);
        PK2(x0, xv0.z); PK2(x1, xv1.z); PK2(f0, fv0.z); PK2(f1, fv1.z);
        stepG16(rg, wa + 2 * WSTR, wb + 2 * WSTR, x0, x1, f0, f1);
        PK2(x0, xv0.w); PK2(x1, xv1.w); PK2(f0, fv0.w); PK2(f1, fv1.w);
        stepG16(rg, wa + 3 * WSTR, wb + 3 * WSTR, x0, x1, f0, f1);
    }
    #pragma unroll
    for (int q = 0; q < 16; q++) {
        float lo, hi; UPK2(lo, hi, rg[q]);
        lo = sigmoid_fast(lo); hi = sigmoid_fast(hi);
        RPK2(rg[q], lo, hi);
    }

    // ---- n gate ----
    __syncthreads();
    loadW2(sW, Wih, Whh, 128, tid);
    __syncthreads();
    ull nv[16];
    {
        const ull* pbi = (const ull*)(sB + 256 + mbase);
        const ull* pbh = (const ull*)(sB + 448 + mbase);
        #pragma unroll
        for (int q = 0; q < 8; q++) {
            nv[q] = pbi[q];   FMA2(nv[q],   rg[q],   pbh[q]);
            nv[8+q] = pbi[q]; FMA2(nv[8+q], rg[8+q], pbh[q]);
        }
    }
    #pragma unroll 2
    for (int k4 = 0; k4 < 16; k4++) {
        float4 xv0 = *(const float4*)(sX + row0 + k4 * 4);
        float4 xv1 = *(const float4*)(sX + row1 + k4 * 4);
        float4 fv0 = *(const float4*)(sF + row0 + k4 * 4);
        float4 fv1 = *(const float4*)(sF + row1 + k4 * 4);
        const float* wa = sW + (k4 * 4) * WSTR + mbase;
        const float* wb = wa + 64 * WSTR;
        ull x0, x1, f0, f1;
        PK2(x0, xv0.x); PK2(x1, xv1.x); PK2(f0, fv0.x); PK2(f1, fv1.x);
        stepN16(nv, rg, wa, wb, x0, x1, f0, f1);
        PK2(x0, xv0.y); PK2(x1, xv1.y); PK2(f0, fv0.y); PK2(f1, fv1.y);
        stepN16(nv, rg, wa + WSTR, wb + WSTR, x0, x1, f0, f1);
        PK2(x0, xv0.z); PK2(x1, xv1.z); PK2(f0, fv0.z); PK2(f1, fv1.z);
        stepN16(nv, rg, wa + 2 * WSTR, wb + 2 * WSTR, x0, x1, f0, f1);
        PK2(x0, xv0.w); PK2(x1, xv1.w); PK2(f0, fv0.w); PK2(f1, fv1.w);
        stepN16(nv, rg, wa + 3 * WSTR, wb + 3 * WSTR, x0, x1, f0, f1);
    }
    #pragma unroll
    for (int q = 0; q < 16; q++) {
        float lo, hi; UPK2(lo, hi, nv[q]);
        lo = tanh_fast(lo); hi = tanh_fast(hi);
        RPK2(nv[q], lo, hi);
    }

    // ---- z gate ----
    __syncthreads();
    loadW2(sW, Wih, Whh, 64, tid);
    __syncthreads();
    ull zg[16];
    {
        const ull* pbi = (const ull*)(sB + 192 + mbase);
        const ull* pbh = (const ull*)(sB + 384 + mbase);
        #pragma unroll
        for (int q = 0; q < 8; q++) { ADD2(zg[q], pbi[q], pbh[q]); zg[8+q] = zg[q]; }
    }
    #pragma unroll 2
    for (int k4 = 0; k4 < 16; k4++) {
        float4 xv0 = *(const float4*)(sX + row0 + k4 * 4);
        float4 xv1 = *(const float4*)(sX + row1 + k4 * 4);
        float4 fv0 = *(const float4*)(sF + row0 + k4 * 4);
        float4 fv1 = *(const float4*)(sF + row1 + k4 * 4);
        const float* wa = sW + (k4 * 4) * WSTR + mbase;
        const float* wb = wa + 64 * WSTR;
        ull x0, x1, f0, f1;
        PK2(x0, xv0.x); PK2(x1, xv1.x); PK2(f0, fv0.x); PK2(f1, fv1.x);
        stepG16(zg, wa, wb, x0, x1, f0, f1);
        PK2(x0, xv0.y); PK2(x1, xv1.y); PK2(f0, fv0.y); PK2(f1, fv1.y);
        stepG16(zg, wa + WSTR, wb + WSTR, x0, x1, f0, f1);
        PK2(x0, xv0.z); PK2(x1, xv1.z); PK2(f0, fv0.z); PK2(f1, fv1.z);
        stepG16(zg, wa + 2 * WSTR, wb + 2 * WSTR, x0, x1, f0, f1);
        PK2(x0, xv0.w); PK2(x1, xv1.w); PK2(f0, fv0.w); PK2(f1, fv1.w);
        stepG16(zg, wa + 3 * WSTR, wb + 3 * WSTR, x0, x1, f0, f1);
    }
    __syncthreads();   // all gate reads of sX done
    // h = n + z*(f - n); park into sX (STS.64)
    #pragma unroll
    for (int q = 0; q < 16; q++) {
        const int row = (q < 8) ? row0 : row1;
        const int mq  = mbase + 2 * (q & 7);
        float zlo, zhi, nlo, nhi;
        UPK2(zlo, zhi, zg[q]); UPK2(nlo, nhi, nv[q]);
        zlo = sigmoid_fast(zlo); zhi = sigmoid_fast(zhi);
        float h0 = nlo + zlo * (sF[row + mq]     - nlo);
        float h1 = nhi + zhi * (sF[row + mq + 1] - nhi);
        ull hp; RPK2(hp, h0, h1);
        *(ull*)(sX + row + mq) = hp;
    }
    // stage classifier weights
    for (int i = tid; i < 1024; i += TPB) {
        int k = i & 63, c = i >> 6;
        sW[k * 16 + c] = Wout[c * 64 + k];
    }
    __syncthreads();

    // ---- classifier: 2 nodes x 4 classes per thread ----
    float oA[4], oB[4];
    #pragma unroll
    for (int c = 0; c < 4; c++) { oA[c] = sB[512 + oq * 4 + c]; oB[c] = oA[c]; }
    #pragma unroll 4
    for (int k4 = 0; k4 < 16; k4++) {
        float4 h0 = *(const float4*)(sX + row0 + k4 * 4);
        float4 h1 = *(const float4*)(sX + row1 + k4 * 4);
        const float* w = sW + (k4 * 4) * 16 + oq * 4;
        float4 w0 = *(const float4*)(w);
        float4 w1 = *(const float4*)(w + 16);
        float4 w2 = *(const float4*)(w + 32);
        float4 w3 = *(const float4*)(w + 48);
        oA[0] += h0.x * w0.x + h0.y * w1.x + h0.z * w2.x + h0.w * w3.x;
        oA[1] += h0.x * w0.y + h0.y * w1.y + h0.z * w2.y + h0.w * w3.y;
        oA[2] += h0.x * w0.z + h0.y * w1.z + h0.z * w2.z + h0.w * w3.z;
        oA[3] += h0.x * w0.w + h0.y * w1.w + h0.z * w2.w + h0.w * w3.w;
        oB[0] += h1.x * w0.x + h1.y * w1.x + h1.z * w2.x + h1.w * w3.x;
        oB[1] += h1.x * w0.y + h1.y * w1.y + h1.z * w2.y + h1.w * w3.y;
        oB[2] += h1.x * w0.z + h1.y * w1.z + h1.z * w2.z + h1.w * w3.z;
        oB[3] += h1.x * w0.w + h1.y * w1.w + h1.z * w2.w + h1.w * w3.w;
    }
    if (nA < Nn)
        *(float4*)(out + (size_t)nA * 16 + oq * 4) = make_float4(oA[0], oA[1], oA[2], oA[3]);
    if (nB < Nn)
        *(float4*)(out + (size_t)nB * 16 + oq * 4) = make_float4(oB[0], oB[1], oB[2], oB[3]);
}

// =====================================================================
extern "C" void kernel_launch(void* const* d_in, const int* in_sizes, int n_in,
                              void* d_out, int out_size)
{
    const float* feat = (const float*)d_in[0];
    const int*   src  = (const int*)d_in[1];
    const int*   dst  = (const int*)d_in[2];
    const void*  et   = d_in[3];
    const float* W0   = (const float*)d_in[4];
    const float* b0   = (const float*)d_in[5];
    const float* W1   = (const float*)d_in[6];
    const float* b1   = (const float*)d_in[7];
    const float* Wih  = (const float*)d_in[8];
    const float* Whh  = (const float*)d_in[9];
    const float* bih  = (const float*)d_in[10];
    const float* bhh  = (const float*)d_in[11];
    const float* Wout = (const float*)d_in[12];
    const float* bout = (const float*)d_in[13];
    float* out = (float*)d_out;

    const int E  = in_sizes[1];
    const int Nn = in_sizes[0] / HDIM;

    void* p;
    cudaGetSymbolAddress(&p, g_cnt);
    cudaMemsetAsync(p, 0, sizeof(int) * 2 * N_NODES);

    detect_et_kernel<<<1, 256>>>((const unsigned char*)et, E);

    place_kernel<<<(E + 255) / 256, 256>>>(src, dst, et, E);

    {
        size_t smem = (size_t)(8704 * 3 + 528) * sizeof(float); // 106560 B
        cudaFuncSetAttribute(node_kernel, cudaFuncAttributeMaxDynamicSharedMemorySize, (int)smem);
        int nb = (Nn + NPB - 1) / NPB;
        node_kernel<<<nb, TPB, smem>>>(feat, W0, b0, W1, b1, Wih, Whh,
                                       bih, bhh, Wout, bout, out, Nn);
    }
}